// round 1
// baseline (speedup 1.0000x reference)
#include <cuda_runtime.h>

#define SS 4
#define GG 3
#define NSG (SS*GG)          // 12
#define NN 20000
#define EE 320000
#define DD 64

// ------------------------- scratch (device globals; no allocations) ---------
__device__ int   g_deg[NSG*NN];
__device__ int   g_rowptr[NSG*(NN+1)];
__device__ int   g_wpos[NSG*NN];
__device__ int   g_csr[NSG*EE];
__device__ float g_mean[NSG*NN*DD];   // 61.4 MB
__device__ float g_h1[NSG*NN*DD];     // 61.4 MB
__device__ float g_h2[NSG*NN*DD];     // 61.4 MB

// ------------------------- MUFU-free math -----------------------------------
__device__ __forceinline__ float frcp_pos(float x) {
    // x > 0. Bit-trick seed + 3 Newton steps: ~1e-7 rel error, all FMA/ALU pipe.
    float y = __uint_as_float(0x7EF311C3u - __float_as_uint(x));
    y = y * (2.0f - x * y);
    y = y * (2.0f - x * y);
    y = y * (2.0f - x * y);
    return y;
}

__device__ __forceinline__ float fast_tanh(float x) {
    // Eigen-style rational minimax on [-7.905, 7.905]; ~1e-7 abs error.
    float cx = fminf(fmaxf(x, -7.90531110763549805f), 7.90531110763549805f);
    float t  = cx * cx;
    float p  = fmaf(t, -2.76076847742355e-16f, 2.00018790482477e-13f);
    p = fmaf(p, t, -8.60467152213735e-11f);
    p = fmaf(p, t,  5.12229709037114e-08f);
    p = fmaf(p, t,  1.48572235717979e-05f);
    p = fmaf(p, t,  6.37261928875436e-04f);
    p = fmaf(p, t,  4.89352455891786e-03f);
    float alpha = cx * p;
    float q = fmaf(t, 1.19825839466702e-06f, 1.18534705686654e-04f);
    q = fmaf(q, t, 2.26843463243900e-03f);
    q = fmaf(q, t, 4.89352518554385e-03f);
    return alpha * frcp_pos(q);
}

__device__ __forceinline__ float fast_sigmoid(float x) {
    return fmaf(0.5f, fast_tanh(0.5f * x), 0.5f);
}

// XOR swizzle for k-major [64][64] smem tiles: element (k, m) lives at
// k*64 + ((m>>2 ^ (k&15))<<2 | (m&3)). Inner-loop reads (k warp-uniform)
// are conflict-free LDS.128; loader writes are <=2-way.
__device__ __forceinline__ int swz(int k, int m) {
    return (k << 6) + ((((m >> 2) ^ (k & 15)) << 2) | (m & 3));
}

// 64-deep k loop: acc[i][j] += A[k][ty*4+i] * W[k][tx*4+j]
__device__ __forceinline__ void mma64(const float* __restrict__ As,
                                      const float* __restrict__ Ws,
                                      int tx, int ty, float acc[4][4]) {
#pragma unroll 16
    for (int k = 0; k < 64; k++) {
        int kk = k & 15;
        float4 a = *(const float4*)(As + (k << 6) + (((ty ^ kk) & 15) << 2));
        float4 w = *(const float4*)(Ws + (k << 6) + (((tx ^ kk) & 15) << 2));
        float av[4] = {a.x, a.y, a.z, a.w};
        float wv[4] = {w.x, w.y, w.z, w.w};
#pragma unroll
        for (int i = 0; i < 4; i++)
#pragma unroll
            for (int j = 0; j < 4; j++)
                acc[i][j] = fmaf(av[i], wv[j], acc[i][j]);
    }
}

// ------------------------- CSR build ----------------------------------------
__global__ void k_zero_deg() {
    int i = blockIdx.x * blockDim.x + threadIdx.x;
    if (i < NSG * NN) g_deg[i] = 0;
}

__global__ void k_count(const int* __restrict__ ei) {
    int e = blockIdx.x * 256 + threadIdx.x;
    int sg = blockIdx.y;
    if (e < EE) {
        int dst = ei[(size_t)(sg * 2 + 1) * EE + e];
        atomicAdd(&g_deg[sg * NN + dst], 1);
    }
}

__global__ void k_scan() {
    __shared__ int part[256];
    __shared__ int excl[257];
    int sg = blockIdx.x, t = threadIdx.x;
    const int C = (NN + 255) / 256;             // 79
    int i0 = t * C, i1 = min(i0 + C, NN);
    int s = 0;
    for (int i = i0; i < i1; i++) s += g_deg[sg * NN + i];
    part[t] = s;
    __syncthreads();
    if (t == 0) {
        int run = 0;
        for (int j = 0; j < 256; j++) { excl[j] = run; run += part[j]; }
        excl[256] = run;
    }
    __syncthreads();
    int run = excl[t];
    for (int i = i0; i < i1; i++) {
        g_rowptr[sg * (NN + 1) + i] = run;
        g_wpos[sg * NN + i] = run;
        run += g_deg[sg * NN + i];
    }
    if (t == 0) g_rowptr[sg * (NN + 1) + NN] = excl[256];
}

__global__ void k_fill(const int* __restrict__ ei) {
    int e = blockIdx.x * 256 + threadIdx.x;
    int sg = blockIdx.y;
    if (e < EE) {
        int src = ei[(size_t)(sg * 2 + 0) * EE + e];
        int dst = ei[(size_t)(sg * 2 + 1) * EE + e];
        int p = atomicAdd(&g_wpos[sg * NN + dst], 1);
        g_csr[(size_t)sg * EE + p] = src;
    }
}

// ------------------------- mean aggregation (gather, no float atomics) ------
__global__ __launch_bounds__(256) void k_agg(const float* __restrict__ xin, int layer) {
    int sg = blockIdx.y;
    int t = threadIdx.x;
    int c = t & 63, rl = t >> 6;
    int i = blockIdx.x * 4 + rl;
    if (i >= NN) return;
    const float* in = layer ? (g_h1 + (size_t)sg * NN * DD)
                            : (xin + (size_t)sg * NN * DD);
    const int* rp = g_rowptr + sg * (NN + 1);
    int e0 = __ldg(rp + i), e1 = __ldg(rp + i + 1);
    const int* cs = g_csr + (size_t)sg * EE;
    float acc = 0.f;
    int e = e0;
    for (; e + 4 <= e1; e += 4) {                 // MLP=4 over dependent gathers
        int s0 = __ldg(cs + e + 0);
        int s1 = __ldg(cs + e + 1);
        int s2 = __ldg(cs + e + 2);
        int s3 = __ldg(cs + e + 3);
        float v0 = __ldg(in + (size_t)s0 * DD + c);
        float v1 = __ldg(in + (size_t)s1 * DD + c);
        float v2 = __ldg(in + (size_t)s2 * DD + c);
        float v3 = __ldg(in + (size_t)s3 * DD + c);
        acc += (v0 + v1) + (v2 + v3);
    }
    for (; e < e1; e++)
        acc += __ldg(in + (size_t)__ldg(cs + e) * DD + c);
    int deg = e1 - e0;
    float m = (deg > 0) ? acc * frcp_pos((float)deg) : 0.f;
    g_mean[(size_t)sg * NN * DD + (size_t)i * DD + c] = m;
}

// ------------------------- SAGE fused GEMM: tanh(mean@Wl + x@Wr + b) --------
__global__ __launch_bounds__(256) void k_gemm(const float* __restrict__ xin, int layer,
                                              const float* __restrict__ Wl_all,
                                              const float* __restrict__ Wr_all,
                                              const float* __restrict__ b_all) {
    __shared__ __align__(16) float As[64 * 64];
    __shared__ __align__(16) float Ws[64 * 64];
    int sg = blockIdx.y, g = sg % GG;
    int t = threadIdx.x, tx = t & 15, ty = t >> 4;
    int row0 = blockIdx.x * 64;

    const float* Aself = layer ? (g_h1 + (size_t)sg * NN * DD)
                               : (xin + (size_t)sg * NN * DD);
    const float* Amean = g_mean + (size_t)sg * NN * DD;
    float* outp = (layer ? g_h2 : g_h1) + (size_t)sg * NN * DD;

    float acc[4][4];
#pragma unroll
    for (int i = 0; i < 4; i++)
#pragma unroll
        for (int j = 0; j < 4; j++) acc[i][j] = 0.f;

    for (int ph = 0; ph < 2; ph++) {
        const float* A = ph ? Aself : Amean;
        const float* W = (ph ? Wr_all : Wl_all) + g * 64 * 64;
        __syncthreads();
        for (int idx = t; idx < 4096; idx += 256) {
            int r = idx >> 6, k = idx & 63;
            int gr = row0 + r;
            As[swz(k, r)] = (gr < NN) ? __ldg(A + (size_t)gr * DD + k) : 0.f;
        }
        for (int idx = t; idx < 4096; idx += 256) {
            int k = idx >> 6, c = idx & 63;
            Ws[swz(k, c)] = __ldg(W + idx);        // W is [k][c] row-major
        }
        __syncthreads();
        mma64(As, Ws, tx, ty, acc);
    }

    float4 bb = *(const float4*)(b_all + g * 64 + tx * 4);
    float bv[4] = {bb.x, bb.y, bb.z, bb.w};
#pragma unroll
    for (int i = 0; i < 4; i++) {
        int gr = row0 + ty * 4 + i;
        if (gr < NN) {
            float4 o;
            o.x = fast_tanh(acc[i][0] + bv[0]);
            o.y = fast_tanh(acc[i][1] + bv[1]);
            o.z = fast_tanh(acc[i][2] + bv[2]);
            o.w = fast_tanh(acc[i][3] + bv[3]);
            *(float4*)(outp + (size_t)gr * DD + tx * 4) = o;
        }
    }
}

// ------------------------- LSTM: 3 steps, 64 rows/block, state in regs/smem -
__global__ __launch_bounds__(256) void k_lstm(const float* __restrict__ Wih,
                                              const float* __restrict__ Whh,
                                              const float* __restrict__ bih,
                                              const float* __restrict__ bhh,
                                              float* __restrict__ outp) {
    __shared__ __align__(16) float xTs[64 * 64];
    __shared__ __align__(16) float hTs[64 * 64];
    __shared__ __align__(16) float Ws[64 * 64];
    int t = threadIdx.x, tx = t & 15, ty = t >> 4;
    int row0 = blockIdx.x * 64;                    // 80000 % 64 == 0, no guards

    for (int idx = t; idx < 4096; idx += 256) hTs[idx] = 0.f;

    float cst[4][4], si[4][4], hv[4][4];
#pragma unroll
    for (int i = 0; i < 4; i++)
#pragma unroll
        for (int j = 0; j < 4; j++) { cst[i][j] = 0.f; hv[i][j] = 0.f; }

    for (int step = 0; step < GG; step++) {
        __syncthreads();                           // prev step fully consumed
        for (int idx = t; idx < 4096; idx += 256) {
            int r = idx >> 6, k = idx & 63;
            int b = row0 + r;
            int s = b / NN, n = b - s * NN;
            xTs[swz(k, r)] =
                __ldg(g_h2 + ((size_t)(s * GG + step) * NN + n) * DD + k);
        }
        for (int p = 0; p < 4; p++) {              // torch gate order: i,f,g,o
            float acc[4][4];
#pragma unroll
            for (int i = 0; i < 4; i++)
#pragma unroll
                for (int j = 0; j < 4; j++) acc[i][j] = 0.f;
            for (int part = 0; part < 2; part++) {
                __syncthreads();                   // Ws free to overwrite
                const float* W = part ? Whh : Wih;
                for (int idx = t; idx < 4096; idx += 256) {
                    int j = idx >> 6, k = idx & 63;
                    Ws[swz(k, j)] = __ldg(W + (size_t)(p * 64 + j) * 64 + k);
                }
                __syncthreads();
                mma64(part ? hTs : xTs, Ws, tx, ty, acc);
            }
            float4 b1v = *(const float4*)(bih + p * 64 + tx * 4);
            float4 b2v = *(const float4*)(bhh + p * 64 + tx * 4);
            float bv[4] = {b1v.x + b2v.x, b1v.y + b2v.y,
                           b1v.z + b2v.z, b1v.w + b2v.w};
            if (p == 0) {
#pragma unroll
                for (int i = 0; i < 4; i++)
#pragma unroll
                    for (int j = 0; j < 4; j++)
                        si[i][j] = fast_sigmoid(acc[i][j] + bv[j]);
            } else if (p == 1) {
#pragma unroll
                for (int i = 0; i < 4; i++)
#pragma unroll
                    for (int j = 0; j < 4; j++)
                        cst[i][j] *= fast_sigmoid(acc[i][j] + bv[j]);
            } else if (p == 2) {
#pragma unroll
                for (int i = 0; i < 4; i++)
#pragma unroll
                    for (int j = 0; j < 4; j++)
                        cst[i][j] = fmaf(si[i][j],
                                         fast_tanh(acc[i][j] + bv[j]),
                                         cst[i][j]);
            } else {
                __syncthreads();                   // all reads of hTs done
#pragma unroll
                for (int i = 0; i < 4; i++)
#pragma unroll
                    for (int j = 0; j < 4; j++) {
                        float h = fast_sigmoid(acc[i][j] + bv[j]) *
                                  fast_tanh(cst[i][j]);
                        hv[i][j] = h;
                        hTs[swz(tx * 4 + j, ty * 4 + i)] = h;
                    }
            }
        }
    }
#pragma unroll
    for (int i = 0; i < 4; i++) {
        int b = row0 + ty * 4 + i;
        float4 o = {hv[i][0], hv[i][1], hv[i][2], hv[i][3]};
        *(float4*)(outp + (size_t)b * DD + tx * 4) = o;
    }
}

// ------------------------- launch -------------------------------------------
extern "C" void kernel_launch(void* const* d_in, const int* in_sizes, int n_in,
                              void* d_out, int out_size) {
    (void)in_sizes; (void)n_in; (void)out_size;
    const float* x   = (const float*)d_in[0];
    const int*   ei  = (const int*)  d_in[1];
    const float* W1l = (const float*)d_in[2];
    const float* W1r = (const float*)d_in[3];
    const float* b1  = (const float*)d_in[4];
    const float* W2l = (const float*)d_in[5];
    const float* W2r = (const float*)d_in[6];
    const float* b2  = (const float*)d_in[7];
    const float* Wih = (const float*)d_in[8];
    const float* Whh = (const float*)d_in[9];
    const float* bih = (const float*)d_in[10];
    const float* bhh = (const float*)d_in[11];
    float* out = (float*)d_out;

    k_zero_deg<<<(NSG * NN + 255) / 256, 256>>>();
    dim3 ge((EE + 255) / 256, NSG);
    k_count<<<ge, 256>>>(ei);
    k_scan<<<NSG, 256>>>();
    k_fill<<<ge, 256>>>(ei);

    dim3 ga((NN + 3) / 4, NSG);
    dim3 gm((NN + 63) / 64, NSG);
    k_agg <<<ga, 256>>>(x, 0);
    k_gemm<<<gm, 256>>>(x, 0, W1l, W1r, b1);
    k_agg <<<ga, 256>>>(x, 1);
    k_gemm<<<gm, 256>>>(x, 1, W2l, W2r, b2);

    k_lstm<<<(SS * NN) / 64, 256>>>(Wih, Whh, bih, bhh, out);
}

// round 4
// speedup vs baseline: 1.8666x; 1.8666x over previous
#include <cuda_runtime.h>
#include <cstdint>

#define SS 4
#define GG 3
#define NSG 12
#define NN 20000
#define EE 320000
#define DD 64
#define BB (SS*NN)   // 80000
#define PAD 68       // float stride: 4*r mod 32 distinct over r -> conflict-free frags

// ------------------------- scratch (device globals; no allocations) ---------
__device__ int   g_deg[NSG*NN];
__device__ int   g_rowptr[NSG*(NN+1)];
__device__ int   g_wpos[NSG*NN];
__device__ int   g_csr[NSG*EE];
__device__ float g_mean[NSG*NN*DD];
__device__ float g_h1[NSG*NN*DD];
__device__ float g_h2[NSG*NN*DD];

// ------------------------- MUFU-free math -----------------------------------
__device__ __forceinline__ float frcp_pos(float x) {
    float y = __uint_as_float(0x7EF311C3u - __float_as_uint(x));
    y = y * (2.0f - x * y);
    y = y * (2.0f - x * y);
    y = y * (2.0f - x * y);
    return y;
}
__device__ __forceinline__ float fast_tanh(float x) {
    float cx = fminf(fmaxf(x, -7.90531110763549805f), 7.90531110763549805f);
    float t  = cx * cx;
    float p  = fmaf(t, -2.76076847742355e-16f, 2.00018790482477e-13f);
    p = fmaf(p, t, -8.60467152213735e-11f);
    p = fmaf(p, t,  5.12229709037114e-08f);
    p = fmaf(p, t,  1.48572235717979e-05f);
    p = fmaf(p, t,  6.37261928875436e-04f);
    p = fmaf(p, t,  4.89352455891786e-03f);
    float alpha = cx * p;
    float q = fmaf(t, 1.19825839466702e-06f, 1.18534705686654e-04f);
    q = fmaf(q, t, 2.26843463243900e-03f);
    q = fmaf(q, t, 4.89352518554385e-03f);
    return alpha * frcp_pos(q);
}
__device__ __forceinline__ float fast_sigmoid(float x) {
    return fmaf(0.5f, fast_tanh(0.5f * x), 0.5f);
}

// ------------------------- tf32 mma.sync helpers -----------------------------
__device__ __forceinline__ float tf32r(float x) {
    uint32_t r;
    asm("cvt.rna.tf32.f32 %0, %1;" : "=r"(r) : "f"(x));
    return __uint_as_float(r);
}
__device__ __forceinline__ void mma8(float acc[4], uint32_t a0, uint32_t a1,
                                     uint32_t a2, uint32_t a3,
                                     uint32_t b0, uint32_t b1) {
    asm("mma.sync.aligned.m16n8k8.row.col.f32.tf32.tf32.f32 "
        "{%0,%1,%2,%3}, {%4,%5,%6,%7}, {%8,%9}, {%0,%1,%2,%3};"
        : "+f"(acc[0]), "+f"(acc[1]), "+f"(acc[2]), "+f"(acc[3])
        : "r"(a0), "r"(a1), "r"(a2), "r"(a3), "r"(b0), "r"(b1));
}
__device__ __forceinline__ uint32_t f2u(float x) { return __float_as_uint(x); }

// ------------------------- CSR build ----------------------------------------
__global__ void k_zero_deg() {
    int i = blockIdx.x * blockDim.x + threadIdx.x;
    if (i < NSG * NN) g_deg[i] = 0;
}
__global__ void k_count(const int* __restrict__ ei) {
    int e = blockIdx.x * 256 + threadIdx.x;
    int sg = blockIdx.y;
    if (e < EE) {
        int dst = ei[(size_t)(sg * 2 + 1) * EE + e];
        atomicAdd(&g_deg[sg * NN + dst], 1);
    }
}
__global__ void k_scan() {
    __shared__ int part[256];
    __shared__ int excl[257];
    int sg = blockIdx.x, t = threadIdx.x;
    const int C = (NN + 255) / 256;
    int i0 = t * C, i1 = min(i0 + C, NN);
    int s = 0;
    for (int i = i0; i < i1; i++) s += g_deg[sg * NN + i];
    part[t] = s;
    __syncthreads();
    if (t == 0) {
        int run = 0;
        for (int j = 0; j < 256; j++) { excl[j] = run; run += part[j]; }
        excl[256] = run;
    }
    __syncthreads();
    int run = excl[t];
    for (int i = i0; i < i1; i++) {
        g_rowptr[sg * (NN + 1) + i] = run;
        g_wpos[sg * NN + i] = run;
        run += g_deg[sg * NN + i];
    }
    if (t == 0) g_rowptr[sg * (NN + 1) + NN] = excl[256];
}
__global__ void k_fill(const int* __restrict__ ei) {
    int e = blockIdx.x * 256 + threadIdx.x;
    int sg = blockIdx.y;
    if (e < EE) {
        int src = ei[(size_t)(sg * 2 + 0) * EE + e];
        int dst = ei[(size_t)(sg * 2 + 1) * EE + e];
        int p = atomicAdd(&g_wpos[sg * NN + dst], 1);
        g_csr[(size_t)sg * EE + p] = src;
    }
}

// ------------------------- mean aggregation (gather) ------------------------
__global__ __launch_bounds__(256) void k_agg(const float* __restrict__ xin, int layer) {
    int sg = blockIdx.y;
    int t = threadIdx.x;
    int c = t & 63, rl = t >> 6;
    int i = blockIdx.x * 4 + rl;
    if (i >= NN) return;
    const float* in = layer ? (g_h1 + (size_t)sg * NN * DD)
                            : (xin + (size_t)sg * NN * DD);
    const int* rp = g_rowptr + sg * (NN + 1);
    int e0 = __ldg(rp + i), e1 = __ldg(rp + i + 1);
    const int* cs = g_csr + (size_t)sg * EE;
    float acc = 0.f;
    int e = e0;
    for (; e + 4 <= e1; e += 4) {
        int s0 = __ldg(cs + e + 0);
        int s1 = __ldg(cs + e + 1);
        int s2 = __ldg(cs + e + 2);
        int s3 = __ldg(cs + e + 3);
        float v0 = __ldg(in + (size_t)s0 * DD + c);
        float v1 = __ldg(in + (size_t)s1 * DD + c);
        float v2 = __ldg(in + (size_t)s2 * DD + c);
        float v3 = __ldg(in + (size_t)s3 * DD + c);
        acc += (v0 + v1) + (v2 + v3);
    }
    for (; e < e1; e++)
        acc += __ldg(in + (size_t)__ldg(cs + e) * DD + c);
    int deg = e1 - e0;
    float m = (deg > 0) ? acc * frcp_pos((float)deg) : 0.f;
    g_mean[(size_t)sg * NN * DD + (size_t)i * DD + c] = m;
}

// ------------------------- SAGE: tanh([mean|x] @ [Wl;Wr] + b), mma.sync tf32
// 128 rows/block, 8 warps, warp-private 16-row m-tiles.
#define SAGE_SMEM ((2*64*PAD + 2*128*PAD + 64) * 4)

__global__ __launch_bounds__(256, 1) void k_sage(const float* __restrict__ x,
        const float* __restrict__ Wl_all, const float* __restrict__ Wr_all,
        const float* __restrict__ b_all, int layer) {
    extern __shared__ float sm[];
    float* Wl_s = sm;
    float* Wr_s = sm + 64 * PAD;
    float* Am_s = sm + 2 * 64 * PAD;
    float* Ax_s = Am_s + 128 * PAD;
    float* bs   = Ax_s + 128 * PAD;
    int t = threadIdx.x, lane = t & 31, w = t >> 5;
    int sg = blockIdx.y, g = sg % GG;
    int row0 = blockIdx.x * 128;
    const float* Aself = (layer ? g_h1 : x) + (size_t)sg * NN * DD;
    const float* Amean = g_mean + (size_t)sg * NN * DD;
    float* outp = (layer ? g_h2 : g_h1) + (size_t)sg * NN * DD;
    const float* Wl = Wl_all + g * 4096;
    const float* Wr = Wr_all + g * 4096;

    for (int idx = t; idx < 4096; idx += 256) {
        int k = idx >> 6, n = idx & 63;
        Wl_s[n * PAD + k] = tf32r(Wl[idx]);       // W given [k][n] -> store [n][k]
        Wr_s[n * PAD + k] = tf32r(Wr[idx]);
    }
    if (t < 64) bs[t] = b_all[g * 64 + t];

#pragma unroll 4
    for (int i = 0; i < 16; i++) {
        int r = w * 16 + i, gr = row0 + r;
        float2 vm = make_float2(0.f, 0.f), vs = vm;
        if (gr < NN) {
            vm = *(const float2*)(Amean + (size_t)gr * DD + 2 * lane);
            vs = *(const float2*)(Aself + (size_t)gr * DD + 2 * lane);
        }
        *(float2*)(Am_s + r * PAD + 2 * lane) = make_float2(tf32r(vm.x), tf32r(vm.y));
        *(float2*)(Ax_s + r * PAD + 2 * lane) = make_float2(tf32r(vs.x), tf32r(vs.y));
    }
    __syncthreads();

    int gq = lane >> 2, t4 = lane & 3;
    float acc[8][4];
#pragma unroll
    for (int nt = 0; nt < 8; nt++)
#pragma unroll
        for (int j = 0; j < 4; j++) acc[nt][j] = 0.f;

#pragma unroll
    for (int part = 0; part < 2; part++) {
        const float* A = part ? Ax_s : Am_s;
        const float* B = part ? Wr_s : Wl_s;
        const float* Ar0 = A + (w * 16 + gq) * PAD;
        const float* Ar1 = Ar0 + 8 * PAD;
#pragma unroll
        for (int kk = 0; kk < 8; kk++) {
            int k0 = kk * 8 + t4;
            uint32_t a0 = f2u(Ar0[k0]),     a1 = f2u(Ar1[k0]);
            uint32_t a2 = f2u(Ar0[k0 + 4]), a3 = f2u(Ar1[k0 + 4]);
#pragma unroll
            for (int nt = 0; nt < 8; nt++) {
                const float* Bp = B + (nt * 8 + gq) * PAD + k0;
                mma8(acc[nt], a0, a1, a2, a3, f2u(Bp[0]), f2u(Bp[4]));
            }
        }
    }

    int r0g = row0 + w * 16 + gq, r1g = r0g + 8;
#pragma unroll
    for (int nt = 0; nt < 8; nt++) {
        int c0 = nt * 8 + t4 * 2;
        float b0v = bs[c0], b1v = bs[c0 + 1];
        if (r0g < NN)
            *(float2*)(outp + (size_t)r0g * DD + c0) =
                make_float2(fast_tanh(acc[nt][0] + b0v), fast_tanh(acc[nt][1] + b1v));
        if (r1g < NN)
            *(float2*)(outp + (size_t)r1g * DD + c0) =
                make_float2(fast_tanh(acc[nt][2] + b0v), fast_tanh(acc[nt][3] + b1v));
    }
}

// ------------------------- LSTM: 3 steps fused, W resident, h/c never leave -
#define LSTM_SMEM ((512*PAD + 2*128*PAD + 256) * 4)

__global__ __launch_bounds__(256, 1) void k_lstm(const float* __restrict__ Wih,
        const float* __restrict__ Whh, const float* __restrict__ bih,
        const float* __restrict__ bhh, float* __restrict__ outp) {
    extern __shared__ float sm[];
    float* Wi_s = sm;                       // [256][PAD]
    float* Wh_s = sm + 256 * PAD;
    float* xT   = sm + 512 * PAD;           // [128][PAD]
    float* hT   = xT + 128 * PAD;
    float* bs   = hT + 128 * PAD;           // 256
    int t = threadIdx.x, lane = t & 31, w = t >> 5;
    int row0 = blockIdx.x * 128;            // 80000 % 128 == 0, no guards

    for (int idx = t; idx < 16384; idx += 256) {
        int n = idx >> 6, k = idx & 63;     // W given [n][k] row-major
        Wi_s[n * PAD + k] = tf32r(Wih[idx]);
        Wh_s[n * PAD + k] = tf32r(Whh[idx]);
    }
    if (t < 256) bs[t] = bih[t] + bhh[t];
    __syncthreads();

    int gq = lane >> 2, t4 = lane & 3;
    const int mrow = w * 16 + gq;
    float cst[8][4], si[8][4];
#pragma unroll
    for (int nt = 0; nt < 8; nt++)
#pragma unroll
        for (int j = 0; j < 4; j++) cst[nt][j] = 0.f;

    for (int step = 0; step < GG; step++) {
        // warp-private x rows for this step
#pragma unroll 4
        for (int i = 0; i < 16; i++) {
            int b = row0 + w * 16 + i;
            int s = b / NN, n = b - s * NN;
            float2 v = *(const float2*)(g_h2 +
                ((size_t)(s * GG + step) * NN + n) * DD + 2 * lane);
            *(float2*)(xT + (w * 16 + i) * PAD + 2 * lane) =
                make_float2(tf32r(v.x), tf32r(v.y));
        }
        __syncwarp();

        for (int gate = 0; gate < 4; gate++) {
            float acc[8][4];
#pragma unroll
            for (int nt = 0; nt < 8; nt++)
#pragma unroll
                for (int j = 0; j < 4; j++) acc[nt][j] = 0.f;

            int nparts = (step > 0) ? 2 : 1;
            for (int part = 0; part < nparts; part++) {
                const float* A = part ? hT : xT;
                const float* B = (part ? Wh_s : Wi_s) + gate * 64 * PAD;
                const float* Ar0 = A + mrow * PAD;
                const float* Ar1 = Ar0 + 8 * PAD;
#pragma unroll
                for (int kk = 0; kk < 8; kk++) {
                    int k0 = kk * 8 + t4;
                    uint32_t a0 = f2u(Ar0[k0]),     a1 = f2u(Ar1[k0]);
                    uint32_t a2 = f2u(Ar0[k0 + 4]), a3 = f2u(Ar1[k0 + 4]);
#pragma unroll
                    for (int nt = 0; nt < 8; nt++) {
                        const float* Bp = B + (nt * 8 + gq) * PAD + k0;
                        mma8(acc[nt], a0, a1, a2, a3, f2u(Bp[0]), f2u(Bp[4]));
                    }
                }
            }

            if (gate == 0) {
#pragma unroll
                for (int nt = 0; nt < 8; nt++) {
                    int c0 = nt * 8 + t4 * 2;
                    si[nt][0] = fast_sigmoid(acc[nt][0] + bs[c0]);
                    si[nt][1] = fast_sigmoid(acc[nt][1] + bs[c0 + 1]);
                    si[nt][2] = fast_sigmoid(acc[nt][2] + bs[c0]);
                    si[nt][3] = fast_sigmoid(acc[nt][3] + bs[c0 + 1]);
                }
            } else if (gate == 1) {
#pragma unroll
                for (int nt = 0; nt < 8; nt++) {
                    int c0 = 64 + nt * 8 + t4 * 2;
                    cst[nt][0] *= fast_sigmoid(acc[nt][0] + bs[c0]);
                    cst[nt][1] *= fast_sigmoid(acc[nt][1] + bs[c0 + 1]);
                    cst[nt][2] *= fast_sigmoid(acc[nt][2] + bs[c0]);
                    cst[nt][3] *= fast_sigmoid(acc[nt][3] + bs[c0 + 1]);
                }
            } else if (gate == 2) {
#pragma unroll
                for (int nt = 0; nt < 8; nt++) {
                    int c0 = 128 + nt * 8 + t4 * 2;
                    cst[nt][0] = fmaf(si[nt][0], fast_tanh(acc[nt][0] + bs[c0]),     cst[nt][0]);
                    cst[nt][1] = fmaf(si[nt][1], fast_tanh(acc[nt][1] + bs[c0 + 1]), cst[nt][1]);
                    cst[nt][2] = fmaf(si[nt][2], fast_tanh(acc[nt][2] + bs[c0]),     cst[nt][2]);
                    cst[nt][3] = fmaf(si[nt][3], fast_tanh(acc[nt][3] + bs[c0 + 1]), cst[nt][3]);
                }
            } else {
#pragma unroll
                for (int nt = 0; nt < 8; nt++) {
                    int c0 = nt * 8 + t4 * 2;
                    float h0 = fast_sigmoid(acc[nt][0] + bs[192 + c0])     * fast_tanh(cst[nt][0]);
                    float h1 = fast_sigmoid(acc[nt][1] + bs[192 + c0 + 1]) * fast_tanh(cst[nt][1]);
                    float h2 = fast_sigmoid(acc[nt][2] + bs[192 + c0])     * fast_tanh(cst[nt][2]);
                    float h3 = fast_sigmoid(acc[nt][3] + bs[192 + c0 + 1]) * fast_tanh(cst[nt][3]);
                    if (step == GG - 1) {
                        int b0 = row0 + mrow;
                        *(float2*)(outp + (size_t)b0 * DD + c0)       = make_float2(h0, h1);
                        *(float2*)(outp + (size_t)(b0 + 8) * DD + c0) = make_float2(h2, h3);
                    } else {
                        *(float2*)(hT + mrow * PAD + c0) =
                            make_float2(tf32r(h0), tf32r(h1));
                        *(float2*)(hT + (mrow + 8) * PAD + c0) =
                            make_float2(tf32r(h2), tf32r(h3));
                    }
                }
            }
        }
        __syncwarp();   // hT writes visible within warp before next step's frags
    }
}

// ------------------------- launch -------------------------------------------
extern "C" void kernel_launch(void* const* d_in, const int* in_sizes, int n_in,
                              void* d_out, int out_size) {
    (void)in_sizes; (void)n_in; (void)out_size;
    const float* x   = (const float*)d_in[0];
    const int*   ei  = (const int*)  d_in[1];
    const float* W1l = (const float*)d_in[2];
    const float* W1r = (const float*)d_in[3];
    const float* b1  = (const float*)d_in[4];
    const float* W2l = (const float*)d_in[5];
    const float* W2r = (const float*)d_in[6];
    const float* b2  = (const float*)d_in[7];
    const float* Wih = (const float*)d_in[8];
    const float* Whh = (const float*)d_in[9];
    const float* bih = (const float*)d_in[10];
    const float* bhh = (const float*)d_in[11];
    float* out = (float*)d_out;

    static int configured = 0;
    cudaFuncSetAttribute(k_sage, cudaFuncAttributeMaxDynamicSharedMemorySize, SAGE_SMEM);
    cudaFuncSetAttribute(k_lstm, cudaFuncAttributeMaxDynamicSharedMemorySize, LSTM_SMEM);
    (void)configured;

    k_zero_deg<<<(NSG * NN + 255) / 256, 256>>>();
    dim3 ge((EE + 255) / 256, NSG);
    k_count<<<ge, 256>>>(ei);
    k_scan<<<NSG, 256>>>();
    k_fill<<<ge, 256>>>(ei);

    dim3 ga((NN + 3) / 4, NSG);
    dim3 gt((NN + 127) / 128, NSG);
    k_agg <<<ga, 256>>>(x, 0);
    k_sage<<<gt, 256, SAGE_SMEM>>>(x, W1l, W1r, b1, 0);
    k_agg <<<ga, 256>>>(x, 1);
    k_sage<<<gt, 256, SAGE_SMEM>>>(x, W2l, W2r, b2, 1);

    k_lstm<<<BB / 128, 256, LSTM_SMEM>>>(Wih, Whh, bih, bhh, out);
}

// round 5
// speedup vs baseline: 2.2661x; 1.2140x over previous
#include <cuda_runtime.h>
#include <cstdint>

#define SS 4
#define GG 3
#define NSG 12
#define NN 20000
#define EE 320000
#define DD 64
#define BB (SS*NN)   // 80000
#define PAD 68

// ------------------------- scratch (device globals; no allocations) ---------
__device__ int   g_deg[NSG*NN];
__device__ int   g_rowptr[NSG*(NN+1)];
__device__ int   g_wpos[NSG*NN];
__device__ int   g_csr[NSG*EE];
__device__ float g_mean[NSG*NN*DD];
__device__ float g_h1[NSG*NN*DD];
__device__ float g_h2[NSG*NN*DD];

// ------------------------- MUFU-free math -----------------------------------
__device__ __forceinline__ float frcp_pos(float x) {
    float y = __uint_as_float(0x7EF311C3u - __float_as_uint(x));
    y = y * (2.0f - x * y);
    y = y * (2.0f - x * y);
    y = y * (2.0f - x * y);
    return y;
}
__device__ __forceinline__ float fast_tanh(float x) {
    float cx = fminf(fmaxf(x, -7.90531110763549805f), 7.90531110763549805f);
    float t  = cx * cx;
    float p  = fmaf(t, -2.76076847742355e-16f, 2.00018790482477e-13f);
    p = fmaf(p, t, -8.60467152213735e-11f);
    p = fmaf(p, t,  5.12229709037114e-08f);
    p = fmaf(p, t,  1.48572235717979e-05f);
    p = fmaf(p, t,  6.37261928875436e-04f);
    p = fmaf(p, t,  4.89352455891786e-03f);
    float alpha = cx * p;
    float q = fmaf(t, 1.19825839466702e-06f, 1.18534705686654e-04f);
    q = fmaf(q, t, 2.26843463243900e-03f);
    q = fmaf(q, t, 4.89352518554385e-03f);
    return alpha * frcp_pos(q);
}
__device__ __forceinline__ float fast_sigmoid(float x) {
    return fmaf(0.5f, fast_tanh(0.5f * x), 0.5f);
}

// ------------------------- tf32 mma.sync helpers -----------------------------
__device__ __forceinline__ float tf32r(float x) {
    uint32_t r;
    asm("cvt.rna.tf32.f32 %0, %1;" : "=r"(r) : "f"(x));
    return __uint_as_float(r);
}
__device__ __forceinline__ void mma8(float acc[4], uint32_t a0, uint32_t a1,
                                     uint32_t a2, uint32_t a3,
                                     uint32_t b0, uint32_t b1) {
    asm("mma.sync.aligned.m16n8k8.row.col.f32.tf32.tf32.f32 "
        "{%0,%1,%2,%3}, {%4,%5,%6,%7}, {%8,%9}, {%0,%1,%2,%3};"
        : "+f"(acc[0]), "+f"(acc[1]), "+f"(acc[2]), "+f"(acc[3])
        : "r"(a0), "r"(a1), "r"(a2), "r"(a3), "r"(b0), "r"(b1));
}
__device__ __forceinline__ uint32_t f2u(float x) { return __float_as_uint(x); }

// ------------------------- CSR build (x4 vectorized) ------------------------
__global__ void k_zero_deg() {
    int i = blockIdx.x * blockDim.x + threadIdx.x;
    if (i < NSG * NN) g_deg[i] = 0;
}
__global__ void k_count(const int* __restrict__ ei) {
    int e4 = (blockIdx.x * 256 + threadIdx.x) * 4;
    int sg = blockIdx.y;
    if (e4 < EE) {
        int4 d = *(const int4*)(ei + (size_t)(sg * 2 + 1) * EE + e4);
        int* base = g_deg + sg * NN;
        atomicAdd(base + d.x, 1);
        atomicAdd(base + d.y, 1);
        atomicAdd(base + d.z, 1);
        atomicAdd(base + d.w, 1);
    }
}
__global__ void k_scan() {
    __shared__ int part[256];
    __shared__ int excl[257];
    int sg = blockIdx.x, t = threadIdx.x;
    const int C = (NN + 255) / 256;
    int i0 = t * C, i1 = min(i0 + C, NN);
    int s = 0;
    for (int i = i0; i < i1; i++) s += g_deg[sg * NN + i];
    part[t] = s;
    __syncthreads();
    if (t == 0) {
        int run = 0;
        for (int j = 0; j < 256; j++) { excl[j] = run; run += part[j]; }
        excl[256] = run;
    }
    __syncthreads();
    int run = excl[t];
    for (int i = i0; i < i1; i++) {
        g_rowptr[sg * (NN + 1) + i] = run;
        g_wpos[sg * NN + i] = run;
        run += g_deg[sg * NN + i];
    }
    if (t == 0) g_rowptr[sg * (NN + 1) + NN] = excl[256];
}
__global__ void k_fill(const int* __restrict__ ei) {
    int e4 = (blockIdx.x * 256 + threadIdx.x) * 4;
    int sg = blockIdx.y;
    if (e4 < EE) {
        int4 s = *(const int4*)(ei + (size_t)(sg * 2 + 0) * EE + e4);
        int4 d = *(const int4*)(ei + (size_t)(sg * 2 + 1) * EE + e4);
        int* wp = g_wpos + sg * NN;
        int* cs = g_csr + (size_t)sg * EE;
        cs[atomicAdd(wp + d.x, 1)] = s.x;
        cs[atomicAdd(wp + d.y, 1)] = s.y;
        cs[atomicAdd(wp + d.z, 1)] = s.z;
        cs[atomicAdd(wp + d.w, 1)] = s.w;
    }
}

// ------------------------- mean aggregation: warp-per-row, MLP=8 ------------
__global__ __launch_bounds__(256) void k_agg(const float* __restrict__ xin, int layer) {
    int sg = blockIdx.y;
    int w = threadIdx.x >> 5, lane = threadIdx.x & 31;
    int i = blockIdx.x * 8 + w;
    if (i >= NN) return;
    const float* in = layer ? (g_h1 + (size_t)sg * NN * DD)
                            : (xin + (size_t)sg * NN * DD);
    const int* rp = g_rowptr + sg * (NN + 1);
    int e0 = __ldg(rp + i), e1 = __ldg(rp + i + 1);
    const int* cs = g_csr + (size_t)sg * EE;
    float ax = 0.f, ay = 0.f;
    int e = e0;
    for (; e + 8 <= e1; e += 8) {
        int idx[8];
#pragma unroll
        for (int u = 0; u < 8; u++) idx[u] = __ldg(cs + e + u);
#pragma unroll
        for (int u = 0; u < 8; u++) {
            float2 v = *(const float2*)(in + (size_t)idx[u] * DD + 2 * lane);
            ax += v.x; ay += v.y;
        }
    }
    for (; e < e1; e++) {
        float2 v = *(const float2*)(in + (size_t)__ldg(cs + e) * DD + 2 * lane);
        ax += v.x; ay += v.y;
    }
    int deg = e1 - e0;
    float r = (deg > 0) ? frcp_pos((float)deg) : 0.f;
    *(float2*)(g_mean + (size_t)sg * NN * DD + (size_t)i * DD + 2 * lane) =
        make_float2(ax * r, ay * r);
}

// ------------------------- SAGE: tanh([mean|x]@[Wl;Wr]+b), mma.sync tf32 ----
#define SAGE_SMEM ((2*64*PAD + 2*128*PAD + 64) * 4)

__global__ __launch_bounds__(256, 1) void k_sage(const float* __restrict__ x,
        const float* __restrict__ Wl_all, const float* __restrict__ Wr_all,
        const float* __restrict__ b_all, int layer) {
    extern __shared__ float sm[];
    float* Wl_s = sm;
    float* Wr_s = sm + 64 * PAD;
    float* Am_s = sm + 2 * 64 * PAD;
    float* Ax_s = Am_s + 128 * PAD;
    float* bs   = Ax_s + 128 * PAD;
    int t = threadIdx.x, lane = t & 31, w = t >> 5;
    int sg = blockIdx.y, g = sg % GG;
    int row0 = blockIdx.x * 128;
    const float* Aself = (layer ? g_h1 : x) + (size_t)sg * NN * DD;
    const float* Amean = g_mean + (size_t)sg * NN * DD;
    float* outp = (layer ? g_h2 : g_h1) + (size_t)sg * NN * DD;
    const float* Wl = Wl_all + g * 4096;
    const float* Wr = Wr_all + g * 4096;

    for (int idx = t; idx < 4096; idx += 256) {
        int k = idx >> 6, n = idx & 63;
        Wl_s[n * PAD + k] = tf32r(Wl[idx]);       // given [k][n] -> store [n][k]
        Wr_s[n * PAD + k] = tf32r(Wr[idx]);
    }
    if (t < 64) bs[t] = b_all[g * 64 + t];

#pragma unroll 4
    for (int i = 0; i < 16; i++) {
        int r = w * 16 + i, gr = row0 + r;
        float2 vm = make_float2(0.f, 0.f), vs = vm;
        if (gr < NN) {
            vm = *(const float2*)(Amean + (size_t)gr * DD + 2 * lane);
            vs = *(const float2*)(Aself + (size_t)gr * DD + 2 * lane);
        }
        *(float2*)(Am_s + r * PAD + 2 * lane) = make_float2(tf32r(vm.x), tf32r(vm.y));
        *(float2*)(Ax_s + r * PAD + 2 * lane) = make_float2(tf32r(vs.x), tf32r(vs.y));
    }
    __syncthreads();

    int gq = lane >> 2, t4 = lane & 3;
    float acc[8][4];
#pragma unroll
    for (int nt = 0; nt < 8; nt++)
#pragma unroll
        for (int j = 0; j < 4; j++) acc[nt][j] = 0.f;

#pragma unroll
    for (int part = 0; part < 2; part++) {
        const float* A = part ? Ax_s : Am_s;
        const float* B = part ? Wr_s : Wl_s;
        const float* Ar0 = A + (w * 16 + gq) * PAD;
        const float* Ar1 = Ar0 + 8 * PAD;
#pragma unroll
        for (int kk = 0; kk < 8; kk++) {
            int k0 = kk * 8 + t4;
            uint32_t a0 = f2u(Ar0[k0]),     a1 = f2u(Ar1[k0]);
            uint32_t a2 = f2u(Ar0[k0 + 4]), a3 = f2u(Ar1[k0 + 4]);
#pragma unroll
            for (int nt = 0; nt < 8; nt++) {
                const float* Bp = B + (nt * 8 + gq) * PAD + k0;
                mma8(acc[nt], a0, a1, a2, a3, f2u(Bp[0]), f2u(Bp[4]));
            }
        }
    }

    int r0g = row0 + w * 16 + gq, r1g = r0g + 8;
#pragma unroll
    for (int nt = 0; nt < 8; nt++) {
        int c0 = nt * 8 + t4 * 2;
        float b0v = bs[c0], b1v = bs[c0 + 1];
        if (r0g < NN)
            *(float2*)(outp + (size_t)r0g * DD + c0) =
                make_float2(fast_tanh(acc[nt][0] + b0v), fast_tanh(acc[nt][1] + b1v));
        if (r1g < NN)
            *(float2*)(outp + (size_t)r1g * DD + c0) =
                make_float2(fast_tanh(acc[nt][2] + b0v), fast_tanh(acc[nt][3] + b1v));
    }
}

// ------------------------- LSTM: persistent-strided, W resident -------------
#define LSTM_SMEM ((512*PAD + 2*128*PAD + 256) * 4)
#define NTILES (BB/128)   // 625
#define LGRID 148

__global__ __launch_bounds__(256, 1) void k_lstm(const float* __restrict__ Wih,
        const float* __restrict__ Whh, const float* __restrict__ bih,
        const float* __restrict__ bhh, float* __restrict__ outp) {
    extern __shared__ float sm[];
    float* Wi_s = sm;                       // [256][PAD]
    float* Wh_s = sm + 256 * PAD;
    float* xT   = sm + 512 * PAD;           // [128][PAD]
    float* hT   = xT + 128 * PAD;
    float* bs   = hT + 128 * PAD;           // 256
    int t = threadIdx.x, lane = t & 31, w = t >> 5;

    for (int idx = t * 4; idx < 16384; idx += 1024) {
        int n = idx >> 6, k = idx & 63;     // W given [n][k] row-major
        float4 vi = *(const float4*)(Wih + idx);
        float4 vh = *(const float4*)(Whh + idx);
        float* wi = Wi_s + n * PAD + k;
        float* wh = Wh_s + n * PAD + k;
        wi[0] = tf32r(vi.x); wi[1] = tf32r(vi.y);
        wi[2] = tf32r(vi.z); wi[3] = tf32r(vi.w);
        wh[0] = tf32r(vh.x); wh[1] = tf32r(vh.y);
        wh[2] = tf32r(vh.z); wh[3] = tf32r(vh.w);
    }
    if (t < 256) bs[t] = bih[t] + bhh[t];
    __syncthreads();

    int gq = lane >> 2, t4 = lane & 3;
    const int mrow = w * 16 + gq;

    for (int tile = blockIdx.x; tile < NTILES; tile += LGRID) {
        int row0 = tile * 128;
        float cst[8][4], si[8][4];
#pragma unroll
        for (int nt = 0; nt < 8; nt++)
#pragma unroll
            for (int j = 0; j < 4; j++) cst[nt][j] = 0.f;

        for (int step = 0; step < GG; step++) {
#pragma unroll 4
            for (int i = 0; i < 16; i++) {
                int b = row0 + w * 16 + i;
                int s = b / NN, n = b - s * NN;
                float2 v = *(const float2*)(g_h2 +
                    ((size_t)(s * GG + step) * NN + n) * DD + 2 * lane);
                *(float2*)(xT + (w * 16 + i) * PAD + 2 * lane) =
                    make_float2(tf32r(v.x), tf32r(v.y));
            }
            __syncwarp();

            for (int gate = 0; gate < 4; gate++) {
                float acc[8][4];
#pragma unroll
                for (int nt = 0; nt < 8; nt++)
#pragma unroll
                    for (int j = 0; j < 4; j++) acc[nt][j] = 0.f;

                int nparts = (step > 0) ? 2 : 1;
                for (int part = 0; part < nparts; part++) {
                    const float* A = part ? hT : xT;
                    const float* B = (part ? Wh_s : Wi_s) + gate * 64 * PAD;
                    const float* Ar0 = A + mrow * PAD;
                    const float* Ar1 = Ar0 + 8 * PAD;
#pragma unroll
                    for (int kk = 0; kk < 8; kk++) {
                        int k0 = kk * 8 + t4;
                        uint32_t a0 = f2u(Ar0[k0]),     a1 = f2u(Ar1[k0]);
                        uint32_t a2 = f2u(Ar0[k0 + 4]), a3 = f2u(Ar1[k0 + 4]);
#pragma unroll
                        for (int nt = 0; nt < 8; nt++) {
                            const float* Bp = B + (nt * 8 + gq) * PAD + k0;
                            mma8(acc[nt], a0, a1, a2, a3, f2u(Bp[0]), f2u(Bp[4]));
                        }
                    }
                }

                if (gate == 0) {
#pragma unroll
                    for (int nt = 0; nt < 8; nt++) {
                        int c0 = nt * 8 + t4 * 2;
                        si[nt][0] = fast_sigmoid(acc[nt][0] + bs[c0]);
                        si[nt][1] = fast_sigmoid(acc[nt][1] + bs[c0 + 1]);
                        si[nt][2] = fast_sigmoid(acc[nt][2] + bs[c0]);
                        si[nt][3] = fast_sigmoid(acc[nt][3] + bs[c0 + 1]);
                    }
                } else if (gate == 1) {
#pragma unroll
                    for (int nt = 0; nt < 8; nt++) {
                        int c0 = 64 + nt * 8 + t4 * 2;
                        cst[nt][0] *= fast_sigmoid(acc[nt][0] + bs[c0]);
                        cst[nt][1] *= fast_sigmoid(acc[nt][1] + bs[c0 + 1]);
                        cst[nt][2] *= fast_sigmoid(acc[nt][2] + bs[c0]);
                        cst[nt][3] *= fast_sigmoid(acc[nt][3] + bs[c0 + 1]);
                    }
                } else if (gate == 2) {
#pragma unroll
                    for (int nt = 0; nt < 8; nt++) {
                        int c0 = 128 + nt * 8 + t4 * 2;
                        cst[nt][0] = fmaf(si[nt][0], fast_tanh(acc[nt][0] + bs[c0]),     cst[nt][0]);
                        cst[nt][1] = fmaf(si[nt][1], fast_tanh(acc[nt][1] + bs[c0 + 1]), cst[nt][1]);
                        cst[nt][2] = fmaf(si[nt][2], fast_tanh(acc[nt][2] + bs[c0]),     cst[nt][2]);
                        cst[nt][3] = fmaf(si[nt][3], fast_tanh(acc[nt][3] + bs[c0 + 1]), cst[nt][3]);
                    }
                } else {
#pragma unroll
                    for (int nt = 0; nt < 8; nt++) {
                        int c0 = nt * 8 + t4 * 2;
                        float h0 = fast_sigmoid(acc[nt][0] + bs[192 + c0])     * fast_tanh(cst[nt][0]);
                        float h1 = fast_sigmoid(acc[nt][1] + bs[192 + c0 + 1]) * fast_tanh(cst[nt][1]);
                        float h2 = fast_sigmoid(acc[nt][2] + bs[192 + c0])     * fast_tanh(cst[nt][2]);
                        float h3 = fast_sigmoid(acc[nt][3] + bs[192 + c0 + 1]) * fast_tanh(cst[nt][3]);
                        if (step == GG - 1) {
                            int b0 = row0 + mrow;
                            *(float2*)(outp + (size_t)b0 * DD + c0)       = make_float2(h0, h1);
                            *(float2*)(outp + (size_t)(b0 + 8) * DD + c0) = make_float2(h2, h3);
                        } else {
                            *(float2*)(hT + mrow * PAD + c0) =
                                make_float2(tf32r(h0), tf32r(h1));
                            *(float2*)(hT + (mrow + 8) * PAD + c0) =
                                make_float2(tf32r(h2), tf32r(h3));
                        }
                    }
                }
            }
            __syncwarp();
        }
    }
}

// ------------------------- launch -------------------------------------------
extern "C" void kernel_launch(void* const* d_in, const int* in_sizes, int n_in,
                              void* d_out, int out_size) {
    (void)in_sizes; (void)n_in; (void)out_size;
    const float* x   = (const float*)d_in[0];
    const int*   ei  = (const int*)  d_in[1];
    const float* W1l = (const float*)d_in[2];
    const float* W1r = (const float*)d_in[3];
    const float* b1  = (const float*)d_in[4];
    const float* W2l = (const float*)d_in[5];
    const float* W2r = (const float*)d_in[6];
    const float* b2  = (const float*)d_in[7];
    const float* Wih = (const float*)d_in[8];
    const float* Whh = (const float*)d_in[9];
    const float* bih = (const float*)d_in[10];
    const float* bhh = (const float*)d_in[11];
    float* out = (float*)d_out;

    cudaFuncSetAttribute(k_sage, cudaFuncAttributeMaxDynamicSharedMemorySize, SAGE_SMEM);
    cudaFuncSetAttribute(k_lstm, cudaFuncAttributeMaxDynamicSharedMemorySize, LSTM_SMEM);

    k_zero_deg<<<(NSG * NN + 255) / 256, 256>>>();
    dim3 ge4((EE / 4 + 255) / 256, NSG);
    k_count<<<ge4, 256>>>(ei);
    k_scan<<<NSG, 256>>>();
    k_fill<<<ge4, 256>>>(ei);

    dim3 ga((NN + 7) / 8, NSG);
    dim3 gt((NN + 127) / 128, NSG);
    k_agg <<<ga, 256>>>(x, 0);
    k_sage<<<gt, 256, SAGE_SMEM>>>(x, W1l, W1r, b1, 0);
    k_agg <<<ga, 256>>>(x, 1);
    k_sage<<<gt, 256, SAGE_SMEM>>>(x, W2l, W2r, b2, 1);

    k_lstm<<<LGRID, 256, LSTM_SMEM>>>(Wih, Whh, bih, bhh, out);
}

// round 6
// speedup vs baseline: 2.5360x; 1.1191x over previous
#include <cuda_runtime.h>
#include <cstdint>

#define SS 4
#define GG 3
#define NSG 12
#define NN 20000
#define EE 320000
#define DD 64
#define BB (SS*NN)   // 80000
#define PAD 68

// ------------------------- scratch (device globals; no allocations) ---------
__device__ int   g_deg[NSG*NN];
__device__ int   g_rowptr[NSG*(NN+1)];
__device__ int   g_wpos[NSG*NN];
__device__ int   g_csr[NSG*EE];
__device__ float g_mean[NSG*NN*DD];
__device__ float g_h1[NSG*NN*DD];
__device__ float g_h2[NSG*NN*DD];

// ------------------------- math ---------------------------------------------
__device__ __forceinline__ float frcp_pos(float x) {
    float y = __uint_as_float(0x7EF311C3u - __float_as_uint(x));
    y = y * (2.0f - x * y);
    y = y * (2.0f - x * y);
    y = y * (2.0f - x * y);
    return y;
}
// HW tanh on the MUFU pipe (sm_75+): 1 op instead of ~18 FMA, off the FMA pipe.
__device__ __forceinline__ float htanh(float x) {
    float y;
    asm("tanh.approx.f32 %0, %1;" : "=f"(y) : "f"(x));
    return y;
}
__device__ __forceinline__ float hsig(float x) {
    return fmaf(0.5f, htanh(0.5f * x), 0.5f);
}

// ------------------------- tf32 mma.sync helpers -----------------------------
__device__ __forceinline__ float tf32r(float x) {
    uint32_t r;
    asm("cvt.rna.tf32.f32 %0, %1;" : "=r"(r) : "f"(x));
    return __uint_as_float(r);
}
__device__ __forceinline__ void mma8(float acc[4], uint32_t a0, uint32_t a1,
                                     uint32_t a2, uint32_t a3,
                                     uint32_t b0, uint32_t b1) {
    asm("mma.sync.aligned.m16n8k8.row.col.f32.tf32.tf32.f32 "
        "{%0,%1,%2,%3}, {%4,%5,%6,%7}, {%8,%9}, {%0,%1,%2,%3};"
        : "+f"(acc[0]), "+f"(acc[1]), "+f"(acc[2]), "+f"(acc[3])
        : "r"(a0), "r"(a1), "r"(a2), "r"(a3), "r"(b0), "r"(b1));
}
__device__ __forceinline__ uint32_t f2u(float x) { return __float_as_uint(x); }

// ------------------------- CSR build (x4 vectorized) ------------------------
__global__ void k_zero_deg() {
    int i = blockIdx.x * blockDim.x + threadIdx.x;
    if (i < NSG * NN) g_deg[i] = 0;
}
__global__ void k_count(const int* __restrict__ ei) {
    int e4 = (blockIdx.x * 256 + threadIdx.x) * 4;
    int sg = blockIdx.y;
    if (e4 < EE) {
        int4 d = *(const int4*)(ei + (size_t)(sg * 2 + 1) * EE + e4);
        int* base = g_deg + sg * NN;
        atomicAdd(base + d.x, 1);
        atomicAdd(base + d.y, 1);
        atomicAdd(base + d.z, 1);
        atomicAdd(base + d.w, 1);
    }
}
__global__ void k_scan() {
    __shared__ int part[256];
    __shared__ int excl[257];
    int sg = blockIdx.x, t = threadIdx.x;
    const int C = (NN + 255) / 256;
    int i0 = t * C, i1 = min(i0 + C, NN);
    int s = 0;
    for (int i = i0; i < i1; i++) s += g_deg[sg * NN + i];
    part[t] = s;
    __syncthreads();
    if (t == 0) {
        int run = 0;
        for (int j = 0; j < 256; j++) { excl[j] = run; run += part[j]; }
        excl[256] = run;
    }
    __syncthreads();
    int run = excl[t];
    for (int i = i0; i < i1; i++) {
        g_rowptr[sg * (NN + 1) + i] = run;
        g_wpos[sg * NN + i] = run;
        run += g_deg[sg * NN + i];
    }
    if (t == 0) g_rowptr[sg * (NN + 1) + NN] = excl[256];
}
__global__ void k_fill(const int* __restrict__ ei) {
    int e4 = (blockIdx.x * 256 + threadIdx.x) * 4;
    int sg = blockIdx.y;
    if (e4 < EE) {
        int4 s = *(const int4*)(ei + (size_t)(sg * 2 + 0) * EE + e4);
        int4 d = *(const int4*)(ei + (size_t)(sg * 2 + 1) * EE + e4);
        int* wp = g_wpos + sg * NN;
        int* cs = g_csr + (size_t)sg * EE;
        cs[atomicAdd(wp + d.x, 1)] = s.x;
        cs[atomicAdd(wp + d.y, 1)] = s.y;
        cs[atomicAdd(wp + d.z, 1)] = s.z;
        cs[atomicAdd(wp + d.w, 1)] = s.w;
    }
}

// ------------------------- mean aggregation: warp-per-row, MLP=8 ------------
__global__ __launch_bounds__(256) void k_agg(const float* __restrict__ xin, int layer) {
    int sg = blockIdx.y;
    int w = threadIdx.x >> 5, lane = threadIdx.x & 31;
    int i = blockIdx.x * 8 + w;
    if (i >= NN) return;
    const float* in = layer ? (g_h1 + (size_t)sg * NN * DD)
                            : (xin + (size_t)sg * NN * DD);
    const int* rp = g_rowptr + sg * (NN + 1);
    int e0 = __ldg(rp + i), e1 = __ldg(rp + i + 1);
    const int* cs = g_csr + (size_t)sg * EE;
    float ax = 0.f, ay = 0.f;
    int e = e0;
    for (; e + 8 <= e1; e += 8) {
        int idx[8];
#pragma unroll
        for (int u = 0; u < 8; u++) idx[u] = __ldg(cs + e + u);
#pragma unroll
        for (int u = 0; u < 8; u++) {
            float2 v = *(const float2*)(in + (size_t)idx[u] * DD + 2 * lane);
            ax += v.x; ay += v.y;
        }
    }
    for (; e < e1; e++) {
        float2 v = *(const float2*)(in + (size_t)__ldg(cs + e) * DD + 2 * lane);
        ax += v.x; ay += v.y;
    }
    int deg = e1 - e0;
    float r = (deg > 0) ? frcp_pos((float)deg) : 0.f;
    *(float2*)(g_mean + (size_t)sg * NN * DD + (size_t)i * DD + 2 * lane) =
        make_float2(ax * r, ay * r);
}

// ------------------------- SAGE: tanh([mean|x]@[Wl;Wr]+b), mma.sync tf32 ----
#define SAGE_SMEM ((2*64*PAD + 2*128*PAD + 64) * 4)

__global__ __launch_bounds__(256, 1) void k_sage(const float* __restrict__ x,
        const float* __restrict__ Wl_all, const float* __restrict__ Wr_all,
        const float* __restrict__ b_all, int layer) {
    extern __shared__ float sm[];
    float* Wl_s = sm;
    float* Wr_s = sm + 64 * PAD;
    float* Am_s = sm + 2 * 64 * PAD;
    float* Ax_s = Am_s + 128 * PAD;
    float* bs   = Ax_s + 128 * PAD;
    int t = threadIdx.x, lane = t & 31, w = t >> 5;
    int sg = blockIdx.y, g = sg % GG;
    int row0 = blockIdx.x * 128;
    const float* Aself = (layer ? g_h1 : x) + (size_t)sg * NN * DD;
    const float* Amean = g_mean + (size_t)sg * NN * DD;
    float* outp = (layer ? g_h2 : g_h1) + (size_t)sg * NN * DD;
    const float* Wl = Wl_all + g * 4096;
    const float* Wr = Wr_all + g * 4096;

    for (int idx = t; idx < 4096; idx += 256) {
        int k = idx >> 6, n = idx & 63;
        Wl_s[n * PAD + k] = tf32r(Wl[idx]);       // given [k][n] -> store [n][k]
        Wr_s[n * PAD + k] = tf32r(Wr[idx]);
    }
    if (t < 64) bs[t] = b_all[g * 64 + t];

#pragma unroll 4
    for (int i = 0; i < 16; i++) {
        int r = w * 16 + i, gr = row0 + r;
        float2 vm = make_float2(0.f, 0.f), vs = vm;
        if (gr < NN) {
            vm = *(const float2*)(Amean + (size_t)gr * DD + 2 * lane);
            vs = *(const float2*)(Aself + (size_t)gr * DD + 2 * lane);
        }
        *(float2*)(Am_s + r * PAD + 2 * lane) = make_float2(tf32r(vm.x), tf32r(vm.y));
        *(float2*)(Ax_s + r * PAD + 2 * lane) = make_float2(tf32r(vs.x), tf32r(vs.y));
    }
    __syncthreads();

    int gq = lane >> 2, t4 = lane & 3;
    float acc[8][4];
#pragma unroll
    for (int nt = 0; nt < 8; nt++)
#pragma unroll
        for (int j = 0; j < 4; j++) acc[nt][j] = 0.f;

#pragma unroll
    for (int part = 0; part < 2; part++) {
        const float* A = part ? Ax_s : Am_s;
        const float* B = part ? Wr_s : Wl_s;
        const float* Ar0 = A + (w * 16 + gq) * PAD;
        const float* Ar1 = Ar0 + 8 * PAD;
#pragma unroll
        for (int kk = 0; kk < 8; kk++) {
            int k0 = kk * 8 + t4;
            uint32_t a0 = f2u(Ar0[k0]),     a1 = f2u(Ar1[k0]);
            uint32_t a2 = f2u(Ar0[k0 + 4]), a3 = f2u(Ar1[k0 + 4]);
#pragma unroll
            for (int nt = 0; nt < 8; nt++) {
                const float* Bp = B + (nt * 8 + gq) * PAD + k0;
                mma8(acc[nt], a0, a1, a2, a3, f2u(Bp[0]), f2u(Bp[4]));
            }
        }
    }

    int r0g = row0 + w * 16 + gq, r1g = r0g + 8;
#pragma unroll
    for (int nt = 0; nt < 8; nt++) {
        int c0 = nt * 8 + t4 * 2;
        float b0v = bs[c0], b1v = bs[c0 + 1];
        if (r0g < NN)
            *(float2*)(outp + (size_t)r0g * DD + c0) =
                make_float2(htanh(acc[nt][0] + b0v), htanh(acc[nt][1] + b1v));
        if (r1g < NN)
            *(float2*)(outp + (size_t)r1g * DD + c0) =
                make_float2(htanh(acc[nt][2] + b0v), htanh(acc[nt][3] + b1v));
    }
}

// ------------------------- LSTM: persistent-strided, W resident -------------
#define LSTM_SMEM ((512*PAD + 2*128*PAD + 256) * 4)
#define NTILES (BB/128)   // 625
#define LGRID 148

__global__ __launch_bounds__(256, 1) void k_lstm(const float* __restrict__ Wih,
        const float* __restrict__ Whh, const float* __restrict__ bih,
        const float* __restrict__ bhh, float* __restrict__ outp) {
    extern __shared__ float sm[];
    float* Wi_s = sm;                       // [256][PAD]
    float* Wh_s = sm + 256 * PAD;
    float* xT   = sm + 512 * PAD;           // [128][PAD]
    float* hT   = xT + 128 * PAD;
    float* bs   = hT + 128 * PAD;           // 256
    int t = threadIdx.x, lane = t & 31, w = t >> 5;

    for (int idx = t * 4; idx < 16384; idx += 1024) {
        int n = idx >> 6, k = idx & 63;     // W given [n][k] row-major
        float4 vi = *(const float4*)(Wih + idx);
        float4 vh = *(const float4*)(Whh + idx);
        float* wi = Wi_s + n * PAD + k;
        float* wh = Wh_s + n * PAD + k;
        wi[0] = tf32r(vi.x); wi[1] = tf32r(vi.y);
        wi[2] = tf32r(vi.z); wi[3] = tf32r(vi.w);
        wh[0] = tf32r(vh.x); wh[1] = tf32r(vh.y);
        wh[2] = tf32r(vh.z); wh[3] = tf32r(vh.w);
    }
    if (t < 256) bs[t] = bih[t] + bhh[t];
    __syncthreads();

    int gq = lane >> 2, t4 = lane & 3;
    const int mrow = w * 16 + gq;

    for (int tile = blockIdx.x; tile < NTILES; tile += LGRID) {
        int row0 = tile * 128;
        float cst[8][4], si[8][4];
#pragma unroll
        for (int nt = 0; nt < 8; nt++)
#pragma unroll
            for (int j = 0; j < 4; j++) cst[nt][j] = 0.f;

        for (int step = 0; step < GG; step++) {
#pragma unroll 4
            for (int i = 0; i < 16; i++) {
                int b = row0 + w * 16 + i;
                int s = b / NN, n = b - s * NN;
                float2 v = *(const float2*)(g_h2 +
                    ((size_t)(s * GG + step) * NN + n) * DD + 2 * lane);
                *(float2*)(xT + (w * 16 + i) * PAD + 2 * lane) =
                    make_float2(tf32r(v.x), tf32r(v.y));
            }
            __syncwarp();

            for (int gate = 0; gate < 4; gate++) {
                float acc[8][4];
#pragma unroll
                for (int nt = 0; nt < 8; nt++)
#pragma unroll
                    for (int j = 0; j < 4; j++) acc[nt][j] = 0.f;

                int nparts = (step > 0) ? 2 : 1;
                for (int part = 0; part < nparts; part++) {
                    const float* A = part ? hT : xT;
                    const float* B = (part ? Wh_s : Wi_s) + gate * 64 * PAD;
                    const float* Ar0 = A + mrow * PAD;
                    const float* Ar1 = Ar0 + 8 * PAD;
#pragma unroll
                    for (int kk = 0; kk < 8; kk++) {
                        int k0 = kk * 8 + t4;
                        uint32_t a0 = f2u(Ar0[k0]),     a1 = f2u(Ar1[k0]);
                        uint32_t a2 = f2u(Ar0[k0 + 4]), a3 = f2u(Ar1[k0 + 4]);
#pragma unroll
                        for (int nt = 0; nt < 8; nt++) {
                            const float* Bp = B + (nt * 8 + gq) * PAD + k0;
                            mma8(acc[nt], a0, a1, a2, a3, f2u(Bp[0]), f2u(Bp[4]));
                        }
                    }
                }

                if (gate == 0) {
#pragma unroll
                    for (int nt = 0; nt < 8; nt++) {
                        int c0 = nt * 8 + t4 * 2;
                        si[nt][0] = hsig(acc[nt][0] + bs[c0]);
                        si[nt][1] = hsig(acc[nt][1] + bs[c0 + 1]);
                        si[nt][2] = hsig(acc[nt][2] + bs[c0]);
                        si[nt][3] = hsig(acc[nt][3] + bs[c0 + 1]);
                    }
                } else if (gate == 1) {
#pragma unroll
                    for (int nt = 0; nt < 8; nt++) {
                        int c0 = 64 + nt * 8 + t4 * 2;
                        cst[nt][0] *= hsig(acc[nt][0] + bs[c0]);
                        cst[nt][1] *= hsig(acc[nt][1] + bs[c0 + 1]);
                        cst[nt][2] *= hsig(acc[nt][2] + bs[c0]);
                        cst[nt][3] *= hsig(acc[nt][3] + bs[c0 + 1]);
                    }
                } else if (gate == 2) {
#pragma unroll
                    for (int nt = 0; nt < 8; nt++) {
                        int c0 = 128 + nt * 8 + t4 * 2;
                        cst[nt][0] = fmaf(si[nt][0], htanh(acc[nt][0] + bs[c0]),     cst[nt][0]);
                        cst[nt][1] = fmaf(si[nt][1], htanh(acc[nt][1] + bs[c0 + 1]), cst[nt][1]);
                        cst[nt][2] = fmaf(si[nt][2], htanh(acc[nt][2] + bs[c0]),     cst[nt][2]);
                        cst[nt][3] = fmaf(si[nt][3], htanh(acc[nt][3] + bs[c0 + 1]), cst[nt][3]);
                    }
                } else {
#pragma unroll
                    for (int nt = 0; nt < 8; nt++) {
                        int c0 = nt * 8 + t4 * 2;
                        float h0 = hsig(acc[nt][0] + bs[192 + c0])     * htanh(cst[nt][0]);
                        float h1 = hsig(acc[nt][1] + bs[192 + c0 + 1]) * htanh(cst[nt][1]);
                        float h2 = hsig(acc[nt][2] + bs[192 + c0])     * htanh(cst[nt][2]);
                        float h3 = hsig(acc[nt][3] + bs[192 + c0 + 1]) * htanh(cst[nt][3]);
                        if (step == GG - 1) {
                            int b0 = row0 + mrow;
                            *(float2*)(outp + (size_t)b0 * DD + c0)       = make_float2(h0, h1);
                            *(float2*)(outp + (size_t)(b0 + 8) * DD + c0) = make_float2(h2, h3);
                        } else {
                            *(float2*)(hT + mrow * PAD + c0) =
                                make_float2(tf32r(h0), tf32r(h1));
                            *(float2*)(hT + (mrow + 8) * PAD + c0) =
                                make_float2(tf32r(h2), tf32r(h3));
                        }
                    }
                }
            }
            __syncwarp();
        }
    }
}

// ------------------------- launch -------------------------------------------
extern "C" void kernel_launch(void* const* d_in, const int* in_sizes, int n_in,
                              void* d_out, int out_size) {
    (void)in_sizes; (void)n_in; (void)out_size;
    const float* x   = (const float*)d_in[0];
    const int*   ei  = (const int*)  d_in[1];
    const float* W1l = (const float*)d_in[2];
    const float* W1r = (const float*)d_in[3];
    const float* b1  = (const float*)d_in[4];
    const float* W2l = (const float*)d_in[5];
    const float* W2r = (const float*)d_in[6];
    const float* b2  = (const float*)d_in[7];
    const float* Wih = (const float*)d_in[8];
    const float* Whh = (const float*)d_in[9];
    const float* bih = (const float*)d_in[10];
    const float* bhh = (const float*)d_in[11];
    float* out = (float*)d_out;

    cudaFuncSetAttribute(k_sage, cudaFuncAttributeMaxDynamicSharedMemorySize, SAGE_SMEM);
    cudaFuncSetAttribute(k_lstm, cudaFuncAttributeMaxDynamicSharedMemorySize, LSTM_SMEM);

    k_zero_deg<<<(NSG * NN + 255) / 256, 256>>>();
    dim3 ge4((EE / 4 + 255) / 256, NSG);
    k_count<<<ge4, 256>>>(ei);
    k_scan<<<NSG, 256>>>();
    k_fill<<<ge4, 256>>>(ei);

    dim3 ga((NN + 7) / 8, NSG);
    dim3 gt((NN + 127) / 128, NSG);
    k_agg <<<ga, 256>>>(x, 0);
    k_sage<<<gt, 256, SAGE_SMEM>>>(x, W1l, W1r, b1, 0);
    k_agg <<<ga, 256>>>(x, 1);
    k_sage<<<gt, 256, SAGE_SMEM>>>(x, W2l, W2r, b2, 1);

    k_lstm<<<LGRID, 256, LSTM_SMEM>>>(Wih, Whh, bih, bhh, out);
}

// round 7
// speedup vs baseline: 2.7011x; 1.0651x over previous
#include <cuda_runtime.h>
#include <cstdint>

#define SS 4
#define GG 3
#define NSG 12
#define NN 20000
#define EE 320000
#define DD 64
#define BB (SS*NN)   // 80000
#define PAD 68

// ------------------------- scratch (device globals; no allocations) ---------
__device__ int   g_deg[NSG*NN];
__device__ int   g_rowptr[NSG*(NN+1)];
__device__ int   g_wpos[NSG*NN];
__device__ int   g_csr[NSG*EE];
__device__ float g_mean[NSG*NN*DD];
__device__ float g_h1[NSG*NN*DD];
__device__ float g_h2[NSG*NN*DD];

// ------------------------- math ---------------------------------------------
__device__ __forceinline__ float frcp_pos(float x) {
    float y = __uint_as_float(0x7EF311C3u - __float_as_uint(x));
    y = y * (2.0f - x * y);
    y = y * (2.0f - x * y);
    y = y * (2.0f - x * y);
    return y;
}
__device__ __forceinline__ float htanh(float x) {
    float y;
    asm("tanh.approx.f32 %0, %1;" : "=f"(y) : "f"(x));
    return y;
}
__device__ __forceinline__ float hsig(float x) {
    return fmaf(0.5f, htanh(0.5f * x), 0.5f);
}

// ------------------------- tf32 mma.sync helpers -----------------------------
__device__ __forceinline__ float tf32r(float x) {
    uint32_t r;
    asm("cvt.rna.tf32.f32 %0, %1;" : "=r"(r) : "f"(x));
    return __uint_as_float(r);
}
__device__ __forceinline__ void mma8(float acc[4], uint32_t a0, uint32_t a1,
                                     uint32_t a2, uint32_t a3,
                                     uint32_t b0, uint32_t b1) {
    asm("mma.sync.aligned.m16n8k8.row.col.f32.tf32.tf32.f32 "
        "{%0,%1,%2,%3}, {%4,%5,%6,%7}, {%8,%9}, {%0,%1,%2,%3};"
        : "+f"(acc[0]), "+f"(acc[1]), "+f"(acc[2]), "+f"(acc[3])
        : "r"(a0), "r"(a1), "r"(a2), "r"(a3), "r"(b0), "r"(b1));
}
__device__ __forceinline__ uint32_t f2u(float x) { return __float_as_uint(x); }

// ------------------------- CSR build (x8 vectorized) ------------------------
__global__ void k_zero_deg() {
    int i = blockIdx.x * blockDim.x + threadIdx.x;
    if (i < NSG * NN) g_deg[i] = 0;
}
__global__ void k_count(const int* __restrict__ ei) {
    int e8 = (blockIdx.x * 256 + threadIdx.x) * 8;
    int sg = blockIdx.y;
    if (e8 < EE) {
        const int* p = ei + (size_t)(sg * 2 + 1) * EE + e8;
        int4 d0 = *(const int4*)p;
        int4 d1 = *(const int4*)(p + 4);
        int* base = g_deg + sg * NN;
        atomicAdd(base + d0.x, 1);
        atomicAdd(base + d0.y, 1);
        atomicAdd(base + d0.z, 1);
        atomicAdd(base + d0.w, 1);
        atomicAdd(base + d1.x, 1);
        atomicAdd(base + d1.y, 1);
        atomicAdd(base + d1.z, 1);
        atomicAdd(base + d1.w, 1);
    }
}
__global__ void k_scan() {
    __shared__ int part[256];
    __shared__ int excl[257];
    int sg = blockIdx.x, t = threadIdx.x;
    const int C = (NN + 255) / 256;
    int i0 = t * C, i1 = min(i0 + C, NN);
    int s = 0;
    for (int i = i0; i < i1; i++) s += g_deg[sg * NN + i];
    part[t] = s;
    __syncthreads();
    if (t == 0) {
        int run = 0;
        for (int j = 0; j < 256; j++) { excl[j] = run; run += part[j]; }
        excl[256] = run;
    }
    __syncthreads();
    int run = excl[t];
    for (int i = i0; i < i1; i++) {
        g_rowptr[sg * (NN + 1) + i] = run;
        g_wpos[sg * NN + i] = run;
        run += g_deg[sg * NN + i];
    }
    if (t == 0) g_rowptr[sg * (NN + 1) + NN] = excl[256];
}
__global__ void k_fill(const int* __restrict__ ei) {
    int e8 = (blockIdx.x * 256 + threadIdx.x) * 8;
    int sg = blockIdx.y;
    if (e8 < EE) {
        const int* ps = ei + (size_t)(sg * 2 + 0) * EE + e8;
        const int* pd = ei + (size_t)(sg * 2 + 1) * EE + e8;
        int4 s0 = *(const int4*)ps, s1 = *(const int4*)(ps + 4);
        int4 d0 = *(const int4*)pd, d1 = *(const int4*)(pd + 4);
        int* wp = g_wpos + sg * NN;
        int* cs = g_csr + (size_t)sg * EE;
        cs[atomicAdd(wp + d0.x, 1)] = s0.x;
        cs[atomicAdd(wp + d0.y, 1)] = s0.y;
        cs[atomicAdd(wp + d0.z, 1)] = s0.z;
        cs[atomicAdd(wp + d0.w, 1)] = s0.w;
        cs[atomicAdd(wp + d1.x, 1)] = s1.x;
        cs[atomicAdd(wp + d1.y, 1)] = s1.y;
        cs[atomicAdd(wp + d1.z, 1)] = s1.z;
        cs[atomicAdd(wp + d1.w, 1)] = s1.w;
    }
}

// ------------------------- mean aggregation: warp-per-row, MLP=8 ------------
__global__ __launch_bounds__(256) void k_agg(const float* __restrict__ xin, int layer) {
    int sg = blockIdx.y;
    int w = threadIdx.x >> 5, lane = threadIdx.x & 31;
    int i = blockIdx.x * 8 + w;
    if (i >= NN) return;
    const float* in = layer ? (g_h1 + (size_t)sg * NN * DD)
                            : (xin + (size_t)sg * NN * DD);
    const int* rp = g_rowptr + sg * (NN + 1);
    int e0 = __ldg(rp + i), e1 = __ldg(rp + i + 1);
    const int* cs = g_csr + (size_t)sg * EE;
    float ax = 0.f, ay = 0.f;
    int e = e0;
    for (; e + 8 <= e1; e += 8) {
        int idx[8];
#pragma unroll
        for (int u = 0; u < 8; u++) idx[u] = __ldg(cs + e + u);
#pragma unroll
        for (int u = 0; u < 8; u++) {
            float2 v = *(const float2*)(in + (size_t)idx[u] * DD + 2 * lane);
            ax += v.x; ay += v.y;
        }
    }
    for (; e < e1; e++) {
        float2 v = *(const float2*)(in + (size_t)__ldg(cs + e) * DD + 2 * lane);
        ax += v.x; ay += v.y;
    }
    int deg = e1 - e0;
    float r = (deg > 0) ? frcp_pos((float)deg) : 0.f;
    *(float2*)(g_mean + (size_t)sg * NN * DD + (size_t)i * DD + 2 * lane) =
        make_float2(ax * r, ay * r);
}

// ------------------------- SAGE: tanh([mean|x]@[Wl;Wr]+b), mma.sync tf32 ----
// B frags lane-ordered float2: Bs2[(nt*8+kk)*32 + lane] = (W[n][k0], W[n][k0+4])
// with n = nt*8 + (lane>>2), k0 = kk*8 + (lane&3). Coalesced LDS.64, 0 conflicts.
#define SAGE_SMEM ((2*2048*2 + 2*128*PAD + 64) * 4)

__global__ __launch_bounds__(256, 1) void k_sage(const float* __restrict__ x,
        const float* __restrict__ Wl_all, const float* __restrict__ Wr_all,
        const float* __restrict__ b_all, int layer) {
    extern __shared__ float sm[];
    float2* Wl2 = (float2*)sm;                  // 2048 float2
    float2* Wr2 = Wl2 + 2048;
    float*  Am_s = sm + 2 * 2048 * 2;
    float*  Ax_s = Am_s + 128 * PAD;
    float*  bs   = Ax_s + 128 * PAD;
    int t = threadIdx.x, lane = t & 31, w = t >> 5;
    int sg = blockIdx.y, g = sg % GG;
    int row0 = blockIdx.x * 128;
    const float* Aself = (layer ? g_h1 : x) + (size_t)sg * NN * DD;
    const float* Amean = g_mean + (size_t)sg * NN * DD;
    float* outp = (layer ? g_h2 : g_h1) + (size_t)sg * NN * DD;
    const float* Wl = Wl_all + g * 4096;        // [k][n] row-major
    const float* Wr = Wr_all + g * 4096;

    for (int idx = t; idx < 2048; idx += 256) {
        int slot = idx >> 5, li = idx & 31;
        int nt = slot >> 3, kk = slot & 7;
        int n = nt * 8 + (li >> 2), k0 = kk * 8 + (li & 3);
        Wl2[idx] = make_float2(tf32r(Wl[k0 * 64 + n]), tf32r(Wl[(k0 + 4) * 64 + n]));
        Wr2[idx] = make_float2(tf32r(Wr[k0 * 64 + n]), tf32r(Wr[(k0 + 4) * 64 + n]));
    }
    if (t < 64) bs[t] = b_all[g * 64 + t];

#pragma unroll 4
    for (int i = 0; i < 16; i++) {
        int r = w * 16 + i, gr = row0 + r;
        float2 vm = make_float2(0.f, 0.f), vs = vm;
        if (gr < NN) {
            vm = *(const float2*)(Amean + (size_t)gr * DD + 2 * lane);
            vs = *(const float2*)(Aself + (size_t)gr * DD + 2 * lane);
        }
        *(float2*)(Am_s + r * PAD + 2 * lane) = make_float2(tf32r(vm.x), tf32r(vm.y));
        *(float2*)(Ax_s + r * PAD + 2 * lane) = make_float2(tf32r(vs.x), tf32r(vs.y));
    }
    __syncthreads();

    int gq = lane >> 2, t4 = lane & 3;
    float acc[8][4];
#pragma unroll
    for (int nt = 0; nt < 8; nt++)
#pragma unroll
        for (int j = 0; j < 4; j++) acc[nt][j] = 0.f;

#pragma unroll
    for (int part = 0; part < 2; part++) {
        const float*  A = part ? Ax_s : Am_s;
        const float2* B = part ? Wr2 : Wl2;
        const float* Ar0 = A + (w * 16 + gq) * PAD;
        const float* Ar1 = Ar0 + 8 * PAD;
#pragma unroll
        for (int kk = 0; kk < 8; kk++) {
            int k0 = kk * 8 + t4;
            uint32_t a0 = f2u(Ar0[k0]),     a1 = f2u(Ar1[k0]);
            uint32_t a2 = f2u(Ar0[k0 + 4]), a3 = f2u(Ar1[k0 + 4]);
#pragma unroll
            for (int nt = 0; nt < 8; nt++) {
                float2 b = B[(nt * 8 + kk) * 32 + lane];
                mma8(acc[nt], a0, a1, a2, a3, f2u(b.x), f2u(b.y));
            }
        }
    }

    int r0g = row0 + w * 16 + gq, r1g = r0g + 8;
#pragma unroll
    for (int nt = 0; nt < 8; nt++) {
        int c0 = nt * 8 + t4 * 2;
        float b0v = bs[c0], b1v = bs[c0 + 1];
        if (r0g < NN)
            *(float2*)(outp + (size_t)r0g * DD + c0) =
                make_float2(htanh(acc[nt][0] + b0v), htanh(acc[nt][1] + b1v));
        if (r1g < NN)
            *(float2*)(outp + (size_t)r1g * DD + c0) =
                make_float2(htanh(acc[nt][2] + b0v), htanh(acc[nt][3] + b1v));
    }
}

// ------------------------- LSTM: persistent-strided, W resident -------------
// Wi2/Wh2 lane-ordered float2 frags: idx = ((gate*8+nt)*8+kk)*32 + lane
#define LSTM_SMEM ((2*8192*2 + 2*128*PAD + 256) * 4)
#define NTILES (BB/128)   // 625
#define LGRID 148

__global__ __launch_bounds__(256, 1) void k_lstm(const float* __restrict__ Wih,
        const float* __restrict__ Whh, const float* __restrict__ bih,
        const float* __restrict__ bhh, float* __restrict__ outp) {
    extern __shared__ float sm[];
    float2* Wi2 = (float2*)sm;              // 8192 float2 = 64 KB
    float2* Wh2 = Wi2 + 8192;
    float*  xT  = sm + 2 * 8192 * 2;        // [128][PAD]
    float*  hT  = xT + 128 * PAD;
    float*  bs  = hT + 128 * PAD;           // 256
    int t = threadIdx.x, lane = t & 31, w = t >> 5;

    for (int idx = t; idx < 8192; idx += 256) {
        int slot = idx >> 5, li = idx & 31;
        int gnt = slot >> 3, kk = slot & 7;         // gnt = gate*8 + nt
        int n = gnt * 8 + (li >> 2), k0 = kk * 8 + (li & 3);
        const float* wi = Wih + (size_t)n * 64;     // [n][k] row-major
        const float* wh = Whh + (size_t)n * 64;
        Wi2[idx] = make_float2(tf32r(wi[k0]), tf32r(wi[k0 + 4]));
        Wh2[idx] = make_float2(tf32r(wh[k0]), tf32r(wh[k0 + 4]));
    }
    if (t < 256) bs[t] = bih[t] + bhh[t];
    __syncthreads();

    int gq = lane >> 2, t4 = lane & 3;
    const int mrow = w * 16 + gq;

    for (int tile = blockIdx.x; tile < NTILES; tile += LGRID) {
        int row0 = tile * 128;
        float cst[8][4], si[8][4];
#pragma unroll
        for (int nt = 0; nt < 8; nt++)
#pragma unroll
            for (int j = 0; j < 4; j++) cst[nt][j] = 0.f;

        for (int step = 0; step < GG; step++) {
#pragma unroll 4
            for (int i = 0; i < 16; i++) {
                int b = row0 + w * 16 + i;
                int s = b / NN, n = b - s * NN;
                float2 v = *(const float2*)(g_h2 +
                    ((size_t)(s * GG + step) * NN + n) * DD + 2 * lane);
                *(float2*)(xT + (w * 16 + i) * PAD + 2 * lane) =
                    make_float2(tf32r(v.x), tf32r(v.y));
            }
            __syncwarp();

            for (int gate = 0; gate < 4; gate++) {
                float acc[8][4];
#pragma unroll
                for (int nt = 0; nt < 8; nt++)
#pragma unroll
                    for (int j = 0; j < 4; j++) acc[nt][j] = 0.f;

                int nparts = (step > 0) ? 2 : 1;
                for (int part = 0; part < nparts; part++) {
                    const float*  A = part ? hT : xT;
                    const float2* B = (part ? Wh2 : Wi2) + gate * 2048;
                    const float* Ar0 = A + mrow * PAD;
                    const float* Ar1 = Ar0 + 8 * PAD;
#pragma unroll
                    for (int kk = 0; kk < 8; kk++) {
                        int k0 = kk * 8 + t4;
                        uint32_t a0 = f2u(Ar0[k0]),     a1 = f2u(Ar1[k0]);
                        uint32_t a2 = f2u(Ar0[k0 + 4]), a3 = f2u(Ar1[k0 + 4]);
#pragma unroll
                        for (int nt = 0; nt < 8; nt++) {
                            float2 b = B[(nt * 8 + kk) * 32 + lane];
                            mma8(acc[nt], a0, a1, a2, a3, f2u(b.x), f2u(b.y));
                        }
                    }
                }

                if (gate == 0) {
#pragma unroll
                    for (int nt = 0; nt < 8; nt++) {
                        int c0 = nt * 8 + t4 * 2;
                        si[nt][0] = hsig(acc[nt][0] + bs[c0]);
                        si[nt][1] = hsig(acc[nt][1] + bs[c0 + 1]);
                        si[nt][2] = hsig(acc[nt][2] + bs[c0]);
                        si[nt][3] = hsig(acc[nt][3] + bs[c0 + 1]);
                    }
                } else if (gate == 1) {
#pragma unroll
                    for (int nt = 0; nt < 8; nt++) {
                        int c0 = 64 + nt * 8 + t4 * 2;
                        cst[nt][0] *= hsig(acc[nt][0] + bs[c0]);
                        cst[nt][1] *= hsig(acc[nt][1] + bs[c0 + 1]);
                        cst[nt][2] *= hsig(acc[nt][2] + bs[c0]);
                        cst[nt][3] *= hsig(acc[nt][3] + bs[c0 + 1]);
                    }
                } else if (gate == 2) {
#pragma unroll
                    for (int nt = 0; nt < 8; nt++) {
                        int c0 = 128 + nt * 8 + t4 * 2;
                        cst[nt][0] = fmaf(si[nt][0], htanh(acc[nt][0] + bs[c0]),     cst[nt][0]);
                        cst[nt][1] = fmaf(si[nt][1], htanh(acc[nt][1] + bs[c0 + 1]), cst[nt][1]);
                        cst[nt][2] = fmaf(si[nt][2], htanh(acc[nt][2] + bs[c0]),     cst[nt][2]);
                        cst[nt][3] = fmaf(si[nt][3], htanh(acc[nt][3] + bs[c0 + 1]), cst[nt][3]);
                    }
                } else {
#pragma unroll
                    for (int nt = 0; nt < 8; nt++) {
                        int c0 = nt * 8 + t4 * 2;
                        float h0 = hsig(acc[nt][0] + bs[192 + c0])     * htanh(cst[nt][0]);
                        float h1 = hsig(acc[nt][1] + bs[192 + c0 + 1]) * htanh(cst[nt][1]);
                        float h2 = hsig(acc[nt][2] + bs[192 + c0])     * htanh(cst[nt][2]);
                        float h3 = hsig(acc[nt][3] + bs[192 + c0 + 1]) * htanh(cst[nt][3]);
                        if (step == GG - 1) {
                            int b0 = row0 + mrow;
                            *(float2*)(outp + (size_t)b0 * DD + c0)       = make_float2(h0, h1);
                            *(float2*)(outp + (size_t)(b0 + 8) * DD + c0) = make_float2(h2, h3);
                        } else {
                            *(float2*)(hT + mrow * PAD + c0) =
                                make_float2(tf32r(h0), tf32r(h1));
                            *(float2*)(hT + (mrow + 8) * PAD + c0) =
                                make_float2(tf32r(h2), tf32r(h3));
                        }
                    }
                }
            }
            __syncwarp();
        }
    }
}

// ------------------------- launch -------------------------------------------
extern "C" void kernel_launch(void* const* d_in, const int* in_sizes, int n_in,
                              void* d_out, int out_size) {
    (void)in_sizes; (void)n_in; (void)out_size;
    const float* x   = (const float*)d_in[0];
    const int*   ei  = (const int*)  d_in[1];
    const float* W1l = (const float*)d_in[2];
    const float* W1r = (const float*)d_in[3];
    const float* b1  = (const float*)d_in[4];
    const float* W2l = (const float*)d_in[5];
    const float* W2r = (const float*)d_in[6];
    const float* b2  = (const float*)d_in[7];
    const float* Wih = (const float*)d_in[8];
    const float* Whh = (const float*)d_in[9];
    const float* bih = (const float*)d_in[10];
    const float* bhh = (const float*)d_in[11];
    float* out = (float*)d_out;

    cudaFuncSetAttribute(k_sage, cudaFuncAttributeMaxDynamicSharedMemorySize, SAGE_SMEM);
    cudaFuncSetAttribute(k_lstm, cudaFuncAttributeMaxDynamicSharedMemorySize, LSTM_SMEM);

    k_zero_deg<<<(NSG * NN + 255) / 256, 256>>>();
    dim3 ge8((EE / 8 + 255) / 256, NSG);
    k_count<<<ge8, 256>>>(ei);
    k_scan<<<NSG, 256>>>();
    k_fill<<<ge8, 256>>>(ei);

    dim3 ga((NN + 7) / 8, NSG);
    dim3 gt((NN + 127) / 128, NSG);
    k_agg <<<ga, 256>>>(x, 0);
    k_sage<<<gt, 256, SAGE_SMEM>>>(x, W1l, W1r, b1, 0);
    k_agg <<<ga, 256>>>(x, 1);
    k_sage<<<gt, 256, SAGE_SMEM>>>(x, W2l, W2r, b2, 1);

    k_lstm<<<LGRID, 256, LSTM_SMEM>>>(Wih, Whh, bih, bhh, out);
}